// round 11
// baseline (speedup 1.0000x reference)
#include <cuda_runtime.h>

#define NT 544

typedef unsigned long long ull;

// Scratch (allowed: __device__ globals, no runtime allocation)
// Conv1 staged-weight image: [chunk][cp][ci_local][k pad 10], cp stride 642 ull.
// 2 chunks x 25 cp x 642 ull. Stored as float2 pairs {w[2cp], w[2cp+1]}.
__device__ __align__(16) float2 g_w1s[2 * 25 * 642];
__device__ float4 g_w2p[64 * 42];        // pconv weights: k padded 3->4
__device__ float2 g_Wt2[128 * 960];      // [(d*8+i)*960 + pair] = {W[p0][d][i], W[p0+1][d][i]}

#define W1S_N (2 * 25 * 642)
#define W2P_N (64 * 42)
#define WT2_N (128 * 960)

__device__ __forceinline__ ull pack2(float lo, float hi) {
    ull r; asm("mov.b64 %0, {%1, %2};" : "=l"(r) : "f"(lo), "f"(hi)); return r;
}
__device__ __forceinline__ void unpack2(ull v, float& lo, float& hi) {
    asm("mov.b64 {%0, %1}, %2;" : "=f"(lo), "=f"(hi) : "l"(v));
}
__device__ __forceinline__ void ffma2(ull& d, ull a, ull b) {
    asm("fma.rn.f32x2 %0, %1, %2, %0;" : "+l"(d) : "l"(a), "l"(b));
}

__global__ void prep_kernel(const float* __restrict__ w1, const float* __restrict__ w2,
                            const float* __restrict__ W) {
    int idx = blockIdx.x * blockDim.x + threadIdx.x;
    if (idx < W1S_N) {
        int chunk = idx / 16050;
        int r = idx - chunk * 16050;
        int cp = r / 642;
        int q = r - cp * 642;
        int cil = q / 10, k = q - cil * 10;
        float lo = 0.f, hi = 0.f;
        if (cil < 64 && k < 9) {
            int ci = chunk * 64 + cil;
            lo = w1[((2 * cp) * 128 + ci) * 9 + k];
            hi = w1[((2 * cp + 1) * 128 + ci) * 9 + k];
        }
        g_w1s[idx] = make_float2(lo, hi);
    } else if (idx < W1S_N + W2P_N) {
        int j = idx - W1S_N;
        const float* s = w2 + j * 3;
        g_w2p[j] = make_float4(s[0], s[1], s[2], 0.f);
    } else {
        int t = idx - (W1S_N + W2P_N);
        if (t < WT2_N) {
            int pair = t % 960;
            int di = t / 960;          // d*8 + i
            int p0 = 2 * pair;
            int o = p0 / 384, c0 = p0 % 384;
            float lo = W[(size_t)o * 49152 + c0 * 128 + di];
            float hi = W[(size_t)o * 49152 + (c0 + 1) * 128 + di];
            g_Wt2[t] = make_float2(lo, hi);
        }
    }
}

// Shared memory layout (floats)
#define OFF_XT    0        // [128][52] stride-1 positions, cols 50/51 zero pad: 6656
#define OFF_H     6656     // [42][51]: 2142 pad 2144
#define OFF_P     8800     // [64][49]: 3136
#define OFF_U     11936    // [384][8]: 3072 (16B aligned)
#define OFF_UHAT  15008    // 5 * 6544 = 32720; aliased as weight stage in phases 1-2
#define OFF_B     47728    // [5][384]: 1920
#define OFF_C     49648    // [5][384]: 1920
#define OFF_SP    51568    // [6][80]: 480
#define OFF_S     52048    // 80
#define OFF_V     52128    // 80
#define OFF_SQ    52208    // 8
#define SMEM_FLTS 52216

#define UH_STRIDE 17
#define O_STRIDE  6544     // 384*17 + 16 pad: == 16 mod 32 words -> o-groups in disjoint bank halves
#define W1_CP_STRIDE 642   // ull stride per cp (64*10 + 2 pad): == 4 mod 32 words

__global__ __launch_bounds__(NT, 1)
void caps_kernel(const float* __restrict__ x,
                 const float* __restrict__ b1,
                 const float* __restrict__ b2,
                 float* __restrict__ out)
{
    extern __shared__ float sm[];
    float* sXT   = sm + OFF_XT;
    float* sH    = sm + OFF_H;
    float* sP    = sm + OFF_P;
    float* sU    = sm + OFF_U;
    float* sUhat = sm + OFF_UHAT;
    float* sB    = sm + OFF_B;
    float* sC    = sm + OFF_C;
    float* sSp   = sm + OFF_SP;
    float* sS    = sm + OFF_S;
    float* sV    = sm + OFF_V;
    float* sSq   = sm + OFF_SQ;

    const int tid = threadIdx.x;
    const int b   = blockIdx.x;

    // ---- Phase 0: load x[b] -> sXT[ci][pos] ----
    {
        const float* xg = x + (size_t)b * 6400;
        for (int i = tid; i < 6400; i += NT) {
            int pos = i >> 7, ci = i & 127;
            sXT[ci * 52 + pos] = xg[i];
        }
        if (tid < 256) {
            int ci = tid >> 1;
            sXT[ci * 52 + 50 + (tid & 1)] = 0.f;
        }
    }
    __syncthreads();

    // ---- Phase 1: conv1 + bias + relu -> sH[l][co], weights staged per 64-ci chunk ----
    // 2co x 4l tile per thread: 25 co-pairs x 11 l-groups = 275 threads
    {
        ull* sW = (ull*)(sm + OFF_UHAT);   // 16050 ull = 32.1K floats, 16B aligned
        int cp = 0, l0 = 0;
        float bb0 = 0.f, bb1 = 0.f;
        ull acc0 = pack2(0.f, 0.f);
        ull acc1 = acc0, acc2 = acc0, acc3 = acc0;
        if (tid < 275) {
            cp = tid / 11;
            l0 = (tid % 11) << 2;
            bb0 = b1[2 * cp]; bb1 = b1[2 * cp + 1];
        }
        for (int chunk = 0; chunk < 2; ++chunk) {
            // stage: straight vector copy of the prep-built image
            {
                const uint4* src = (const uint4*)g_w1s + chunk * 8025;
                uint4* dst = (uint4*)sW;
                for (int i = tid; i < 8025; i += NT) dst[i] = src[i];
            }
            __syncthreads();
            if (tid < 275) {
                const ull* wrow = sW + cp * W1_CP_STRIDE;
                for (int cil = 0; cil < 64; ++cil) {
                    int ci = (chunk << 6) + cil;
                    const float4* xr = (const float4*)(sXT + ci * 52 + l0);
                    float4 xa = xr[0], xb = xr[1], xc = xr[2];
                    ull xd[12];
                    xd[0]  = pack2(xa.x, xa.x); xd[1]  = pack2(xa.y, xa.y);
                    xd[2]  = pack2(xa.z, xa.z); xd[3]  = pack2(xa.w, xa.w);
                    xd[4]  = pack2(xb.x, xb.x); xd[5]  = pack2(xb.y, xb.y);
                    xd[6]  = pack2(xb.z, xb.z); xd[7]  = pack2(xb.w, xb.w);
                    xd[8]  = pack2(xc.x, xc.x); xd[9]  = pack2(xc.y, xc.y);
                    xd[10] = pack2(xc.z, xc.z); xd[11] = pack2(xc.w, xc.w);
                    const ull* wp = wrow + cil * 10;
                    ulonglong2 q0 = *(const ulonglong2*)(wp);
                    ulonglong2 q1 = *(const ulonglong2*)(wp + 2);
                    ulonglong2 q2 = *(const ulonglong2*)(wp + 4);
                    ulonglong2 q3 = *(const ulonglong2*)(wp + 6);
                    ull w8 = wp[8];
                    ull wk[9] = {q0.x, q0.y, q1.x, q1.y, q2.x, q2.y, q3.x, q3.y, w8};
                    #pragma unroll
                    for (int k = 0; k < 9; ++k) {
                        ffma2(acc0, wk[k], xd[k]);
                        ffma2(acc1, wk[k], xd[k + 1]);
                        ffma2(acc2, wk[k], xd[k + 2]);
                        ffma2(acc3, wk[k], xd[k + 3]);
                    }
                }
            }
            __syncthreads();
        }
        if (tid < 275) {
            int co0 = cp << 1;
            float y0a, y0b, y1a, y1b, y2a, y2b, y3a, y3b;
            unpack2(acc0, y0a, y0b);
            unpack2(acc1, y1a, y1b);
            unpack2(acc2, y2a, y2b);
            unpack2(acc3, y3a, y3b);
            float ya[4] = {y0a, y1a, y2a, y3a};
            float yb[4] = {y0b, y1b, y2b, y3b};
            #pragma unroll
            for (int m = 0; m < 4; ++m) {
                int l = l0 + m;
                if (l < 42) {
                    sH[l * 51 + co0]     = fmaxf(ya[m] + bb0, 0.f);
                    sH[l * 51 + co0 + 1] = fmaxf(yb[m] + bb1, 0.f);
                }
            }
        }
    }
    __syncthreads();

    // ---- Phase 2: pconv -> sP[po][t], weights staged in smem ----
    {
        float4* sW2 = (float4*)(sm + OFF_UHAT);   // 2688 float4 = 43KB
        for (int i = tid; i < 2688; i += NT) sW2[i] = g_w2p[i];
        __syncthreads();
        if (tid < 512) {
            int po = tid >> 3, tg = tid & 7;
            int t0 = tg * 6;
            float bias = b2[po];
            float acc[6] = {0.f, 0.f, 0.f, 0.f, 0.f, 0.f};
            const float4* w2r = sW2 + po * 42;
            for (int a = 0; a < 42; ++a) {
                float4 w = w2r[a];
                const float* hr = sH + a * 51 + t0;
                float xv[8];
                #pragma unroll
                for (int r = 0; r < 8; ++r) xv[r] = hr[r];
                #pragma unroll
                for (int j = 0; j < 6; ++j)
                    acc[j] += w.x * xv[j] + w.y * xv[j + 1] + w.z * xv[j + 2];
            }
            #pragma unroll
            for (int j = 0; j < 6; ++j) sP[po * 49 + t0 + j] = acc[j] + bias;
        }
    }
    __syncthreads();

    // ---- Phase 3: primary-caps squash -> sU[c][i] ----
    if (tid < 384) {
        int po = tid / 6, g = tid % 6;
        const float* pr = sP + po * 49 + g * 8;
        float q[8];
        float sq = 0.f;
        #pragma unroll
        for (int i = 0; i < 8; ++i) { q[i] = pr[i]; sq += q[i] * q[i]; }
        float scale = (sq / (1.f + sq)) / (sqrtf(sq) + 1e-8f);
        #pragma unroll
        for (int i = 0; i < 8; ++i) sU[tid * 8 + i] = q[i] * scale;
    }
    __syncthreads();

    // ---- Phase 4: u_hat via transposed W (coalesced), 2 capsules per thread-job ----
    {
        const ull* Wt = (const ull*)g_Wt2;
        for (int pair = tid; pair < 960; pair += NT) {
            int o = pair / 192;              // p0 = 2*pair, o = p0/384
            int c0 = 2 * pair - o * 384;
            const float4* ua = (const float4*)(sU + c0 * 8);
            float4 A0 = ua[0], A1 = ua[1];   // u[c0]
            float4 B0 = ua[2], B1 = ua[3];   // u[c0+1]
            ull uu[8];
            uu[0] = pack2(A0.x, B0.x); uu[1] = pack2(A0.y, B0.y);
            uu[2] = pack2(A0.z, B0.z); uu[3] = pack2(A0.w, B0.w);
            uu[4] = pack2(A1.x, B1.x); uu[5] = pack2(A1.y, B1.y);
            uu[6] = pack2(A1.z, B1.z); uu[7] = pack2(A1.w, B1.w);
            float* uh0 = sUhat + o * O_STRIDE + c0 * UH_STRIDE;
            float* uh1 = uh0 + UH_STRIDE;
            const ull* wp = Wt + pair;
            #pragma unroll
            for (int d = 0; d < 16; ++d) {
                ull acc = pack2(0.f, 0.f);
                #pragma unroll
                for (int i = 0; i < 8; ++i)
                    ffma2(acc, wp[(d * 8 + i) * 960], uu[i]);
                float r0, r1;
                unpack2(acc, r0, r1);
                uh0[d] = r0;
                uh1[d] = r1;
            }
        }
    }
    for (int i = tid; i < 1920; i += NT) sB[i] = 0.f;
    __syncthreads();

    // ---- Phase 5: dynamic routing (3 iterations) ----
    for (int it = 0; it < 3; ++it) {
        // c = softmax over o (axis of size 5), per capsule c
        if (tid < 384) {
            float bb[5], m = -1e30f;
            #pragma unroll
            for (int o = 0; o < 5; ++o) { bb[o] = sB[o * 384 + tid]; m = fmaxf(m, bb[o]); }
            float e[5], ssum = 0.f;
            #pragma unroll
            for (int o = 0; o < 5; ++o) { e[o] = expf(bb[o] - m); ssum += e[o]; }
            float inv = 1.f / ssum;
            #pragma unroll
            for (int o = 0; o < 5; ++o) sC[o * 384 + tid] = e[o] * inv;
        }
        __syncthreads();
        // s[o][d] = sum_c c[o][c] * u_hat[o][c][d]  (6-way split over c)
        if (tid < 480) {
            int od = tid % 80, ch = tid / 80;
            int o = od >> 4, d = od & 15;
            const float* uh = sUhat + o * O_STRIDE + d;
            const float* cc = sC + o * 384;
            float acc = 0.f;
            int c0 = ch * 64;
            for (int c = c0; c < c0 + 64; ++c) acc += cc[c] * uh[c * UH_STRIDE];
            sSp[ch * 80 + od] = acc;
        }
        __syncthreads();
        if (tid < 80) {
            float s = 0.f;
            #pragma unroll
            for (int ch = 0; ch < 6; ++ch) s += sSp[ch * 80 + tid];
            sS[tid] = s;
        }
        __syncthreads();
        if (tid < 5) {
            float sq = 0.f;
            #pragma unroll
            for (int d = 0; d < 16; ++d) { float v = sS[tid * 16 + d]; sq += v * v; }
            sSq[tid] = sq;
        }
        __syncthreads();
        if (tid < 80) {
            int o = tid >> 4;
            float sq = sSq[o];
            float v = sS[tid] * (sq / (1.f + sq)) / (sqrtf(sq) + 1e-8f);
            sV[tid] = v;
            if (it == 2) out[(size_t)b * 80 + tid] = v;
        }
        __syncthreads();
        if (it < 2) {
            // b[o][c] += sum_d u_hat[o][c][d] * v[o][d]  (scalar, conflict-free)
            for (int p = tid; p < 1920; p += NT) {
                int o = p / 384;
                int c = p - o * 384;
                const float* uh = sUhat + o * O_STRIDE + c * UH_STRIDE;
                const float* vv = sV + o * 16;
                float acc = 0.f;
                #pragma unroll
                for (int q = 0; q < 16; ++q) acc += uh[q] * vv[q];
                sB[p] += acc;
            }
            __syncthreads();
        }
    }
}

extern "C" void kernel_launch(void* const* d_in, const int* in_sizes, int n_in,
                              void* d_out, int out_size) {
    const float* x  = (const float*)d_in[0];
    const float* w1 = (const float*)d_in[1];
    const float* b1 = (const float*)d_in[2];
    const float* w2 = (const float*)d_in[3];
    const float* b2 = (const float*)d_in[4];
    const float* W  = (const float*)d_in[5];
    float* out = (float*)d_out;

    int B = in_sizes[0] / 6400;

    size_t smem_bytes = SMEM_FLTS * sizeof(float);
    cudaFuncSetAttribute(caps_kernel, cudaFuncAttributeMaxDynamicSharedMemorySize,
                         (int)smem_bytes);

    int prep_n = W1S_N + W2P_N + WT2_N;
    prep_kernel<<<(prep_n + 255) / 256, 256>>>(w1, w2, W);
    caps_kernel<<<B, NT, smem_bytes>>>(x, b1, b2, out);
}

// round 12
// speedup vs baseline: 1.7996x; 1.7996x over previous
#include <cuda_runtime.h>

#define NT 544

typedef unsigned long long ull;

// Scratch (allowed: __device__ globals, no runtime allocation)
// Conv1 weight image: [chunk][cp][h][cil][k], h stride 290 ull, cp stride 580 ull.
// float2 = {w1[2cp][ci][k], w1[2cp+1][ci][k]}, ci = chunk*64 + h*32 + cil.
__device__ __align__(16) float2 g_w1s2[2 * 25 * 580];
__device__ float4 g_w2p[64 * 42];        // pconv weights: k padded 3->4
__device__ float2 g_Wt2[128 * 960];      // [(d*8+i)*960 + pair] = {W[p0][d][i], W[p0+1][d][i]}

#define W1S_N (2 * 25 * 580)
#define W2P_N (64 * 42)
#define WT2_N (128 * 960)

__device__ __forceinline__ ull pack2(float lo, float hi) {
    ull r; asm("mov.b64 %0, {%1, %2};" : "=l"(r) : "f"(lo), "f"(hi)); return r;
}
__device__ __forceinline__ void unpack2(ull v, float& lo, float& hi) {
    asm("mov.b64 {%0, %1}, %2;" : "=f"(lo), "=f"(hi) : "l"(v));
}
__device__ __forceinline__ void ffma2(ull& d, ull a, ull b) {
    asm("fma.rn.f32x2 %0, %1, %2, %0;" : "+l"(d) : "l"(a), "l"(b));
}

__global__ void prep_kernel(const float* __restrict__ w1, const float* __restrict__ w2,
                            const float* __restrict__ W) {
    int idx = blockIdx.x * blockDim.x + threadIdx.x;
    if (idx < W1S_N) {
        int chunk = idx / 14500;
        int r = idx - chunk * 14500;
        int cp = r / 580;
        int q = r - cp * 580;
        int h = q / 290;
        int w = q - h * 290;
        int cil = w / 9, k = w - cil * 9;
        float lo = 0.f, hi = 0.f;
        if (w < 288) {
            int ci = chunk * 64 + h * 32 + cil;
            lo = w1[((2 * cp) * 128 + ci) * 9 + k];
            hi = w1[((2 * cp + 1) * 128 + ci) * 9 + k];
        }
        g_w1s2[idx] = make_float2(lo, hi);
    } else if (idx < W1S_N + W2P_N) {
        int j = idx - W1S_N;
        const float* s = w2 + j * 3;
        g_w2p[j] = make_float4(s[0], s[1], s[2], 0.f);
    } else {
        int t = idx - (W1S_N + W2P_N);
        if (t < WT2_N) {
            int pair = t % 960;
            int di = t / 960;          // d*8 + i
            int p0 = 2 * pair;
            int o = p0 / 384, c0 = p0 % 384;
            float lo = W[(size_t)o * 49152 + c0 * 128 + di];
            float hi = W[(size_t)o * 49152 + (c0 + 1) * 128 + di];
            g_Wt2[t] = make_float2(lo, hi);
        }
    }
}

// x row addressing: 52 words/row + 8-word pad per 32-ci group (de-aliases ci-halves)
__device__ __forceinline__ int XROW(int ci) { return ci * 52 + ((ci >> 5) << 3); }

// Shared memory layout (floats)
#define OFF_XT    0        // XROW space: 128*52 + 4*8 = 6688
#define OFF_H     6688     // [42][51]: 2142 pad 2144
#define OFF_P     8832     // [64][49]: 3136 (also phase-1 partial scratch 2100)
#define OFF_U     11968    // [384][8]: 3072 (16B aligned)
#define OFF_UHAT  15040    // 5 * 6544 = 32720; aliased as weight stage in phases 1-2
#define OFF_B     47760    // [5][384]: 1920
#define OFF_C     49680    // [5][384]: 1920
#define OFF_SP    51600    // [6][80]: 480
#define OFF_S     52080    // 80
#define OFF_V     52160    // 80
#define OFF_SQ    52240    // 8
#define SMEM_FLTS 52248

#define UH_STRIDE 17
#define O_STRIDE  6544     // 384*17 + 16 pad

__global__ __launch_bounds__(NT, 1)
void caps_kernel(const float* __restrict__ x,
                 const float* __restrict__ b1,
                 const float* __restrict__ b2,
                 float* __restrict__ out)
{
    extern __shared__ float sm[];
    float* sXT   = sm + OFF_XT;
    float* sH    = sm + OFF_H;
    float* sP    = sm + OFF_P;
    float* sU    = sm + OFF_U;
    float* sUhat = sm + OFF_UHAT;
    float* sB    = sm + OFF_B;
    float* sC    = sm + OFF_C;
    float* sSp   = sm + OFF_SP;
    float* sS    = sm + OFF_S;
    float* sV    = sm + OFF_V;
    float* sSq   = sm + OFF_SQ;

    const int tid = threadIdx.x;
    const int b   = blockIdx.x;

    // ---- Phase 0: load x[b] -> sXT[XROW(ci) + pos] ----
    {
        const float* xg = x + (size_t)b * 6400;
        for (int i = tid; i < 6400; i += NT) {
            int pos = i >> 7, ci = i & 127;
            sXT[XROW(ci) + pos] = xg[i];
        }
        if (tid < 256) {
            int ci = tid >> 1;
            sXT[XROW(ci) + 50 + (tid & 1)] = 0.f;
        }
    }
    __syncthreads();

    // ---- Phase 1: conv1 + bias + relu -> sH[l][co] ----
    // 350 threads: cp(0..24) x lg(0..6, 6 l each) x h(ci-half).
    {
        ull* sW = (ull*)(sm + OFF_UHAT);   // 14500 ull per chunk, 16B aligned
        int cp = 0, lg = 0, h = 0, l0 = 0;
        ull acc[6];
        #pragma unroll
        for (int j = 0; j < 6; ++j) acc[j] = pack2(0.f, 0.f);
        if (tid < 350) {
            cp = tid / 14;
            int r = tid - cp * 14;
            lg = r >> 1;
            h  = r & 1;
            l0 = lg * 6;
        }
        for (int chunk = 0; chunk < 2; ++chunk) {
            // stage this chunk's weight image (116KB) via vector copy
            {
                const uint4* src = (const uint4*)g_w1s2 + chunk * 7250;
                uint4* dst = (uint4*)sW;
                for (int i = tid; i < 7250; i += NT) dst[i] = src[i];
            }
            __syncthreads();
            if (tid < 350) {
                const ull* wbase = sW + cp * 580 + h * 290;
                int cibase = chunk * 64 + h * 32;
                for (int cil = 0; cil < 32; ++cil) {
                    int ci = cibase + cil;
                    const float2* xr = (const float2*)(sXT + XROW(ci) + l0);
                    float2 x0 = xr[0], x1 = xr[1], x2 = xr[2], x3 = xr[3];
                    float2 x4 = xr[4], x5 = xr[5], x6 = xr[6];
                    ull xd[14];
                    xd[0]  = pack2(x0.x, x0.x); xd[1]  = pack2(x0.y, x0.y);
                    xd[2]  = pack2(x1.x, x1.x); xd[3]  = pack2(x1.y, x1.y);
                    xd[4]  = pack2(x2.x, x2.x); xd[5]  = pack2(x2.y, x2.y);
                    xd[6]  = pack2(x3.x, x3.x); xd[7]  = pack2(x3.y, x3.y);
                    xd[8]  = pack2(x4.x, x4.x); xd[9]  = pack2(x4.y, x4.y);
                    xd[10] = pack2(x5.x, x5.x); xd[11] = pack2(x5.y, x5.y);
                    xd[12] = pack2(x6.x, x6.x); xd[13] = pack2(x6.y, x6.y);
                    const ull* wp = wbase + cil * 9;
                    ull wk[9];
                    #pragma unroll
                    for (int k = 0; k < 9; ++k) wk[k] = wp[k];
                    #pragma unroll
                    for (int k = 0; k < 9; ++k) {
                        #pragma unroll
                        for (int j = 0; j < 6; ++j)
                            ffma2(acc[j], wk[k], xd[k + j]);
                    }
                }
            }
            __syncthreads();
        }
        // reduce the two ci-halves: h=1 stores partials, h=0 combines
        float* sPart = sP;   // scratch (overwritten by phase 2 output later)
        if (tid < 350 && h == 1) {
            int pi = tid >> 1;
            #pragma unroll
            for (int j = 0; j < 6; ++j) {
                float a, c;
                unpack2(acc[j], a, c);
                sPart[pi * 12 + 2 * j]     = a;
                sPart[pi * 12 + 2 * j + 1] = c;
            }
        }
        __syncthreads();
        if (tid < 350 && h == 0) {
            int pi = tid >> 1;
            int co0 = cp << 1;
            float bb0 = b1[co0], bb1 = b1[co0 + 1];
            #pragma unroll
            for (int j = 0; j < 6; ++j) {
                float a, c;
                unpack2(acc[j], a, c);
                a += sPart[pi * 12 + 2 * j];
                c += sPart[pi * 12 + 2 * j + 1];
                int l = l0 + j;
                sH[l * 51 + co0]     = fmaxf(a + bb0, 0.f);
                sH[l * 51 + co0 + 1] = fmaxf(c + bb1, 0.f);
            }
        }
    }
    __syncthreads();

    // ---- Phase 2: pconv -> sP[po][t], weights staged in smem ----
    {
        float4* sW2 = (float4*)(sm + OFF_UHAT);   // 2688 float4 = 43KB
        for (int i = tid; i < 2688; i += NT) sW2[i] = g_w2p[i];
        __syncthreads();
        if (tid < 512) {
            int po = tid >> 3, tg = tid & 7;
            int t0 = tg * 6;
            float bias = b2[po];
            float acc[6] = {0.f, 0.f, 0.f, 0.f, 0.f, 0.f};
            const float4* w2r = sW2 + po * 42;
            for (int a = 0; a < 42; ++a) {
                float4 w = w2r[a];
                const float* hr = sH + a * 51 + t0;
                float xv[8];
                #pragma unroll
                for (int r = 0; r < 8; ++r) xv[r] = hr[r];
                #pragma unroll
                for (int j = 0; j < 6; ++j)
                    acc[j] += w.x * xv[j] + w.y * xv[j + 1] + w.z * xv[j + 2];
            }
            #pragma unroll
            for (int j = 0; j < 6; ++j) sP[po * 49 + t0 + j] = acc[j] + bias;
        }
    }
    __syncthreads();

    // ---- Phase 3: primary-caps squash -> sU[c][i] ----
    if (tid < 384) {
        int po = tid / 6, g = tid % 6;
        const float* pr = sP + po * 49 + g * 8;
        float q[8];
        float sq = 0.f;
        #pragma unroll
        for (int i = 0; i < 8; ++i) { q[i] = pr[i]; sq += q[i] * q[i]; }
        float scale = (sq / (1.f + sq)) / (sqrtf(sq) + 1e-8f);
        #pragma unroll
        for (int i = 0; i < 8; ++i) sU[tid * 8 + i] = q[i] * scale;
    }
    __syncthreads();

    // ---- Phase 4: u_hat via transposed W (coalesced), 2 capsules per thread-job ----
    {
        const ull* Wt = (const ull*)g_Wt2;
        for (int pair = tid; pair < 960; pair += NT) {
            int o = pair / 192;              // p0 = 2*pair, o = p0/384
            int c0 = 2 * pair - o * 384;
            const float4* ua = (const float4*)(sU + c0 * 8);
            float4 A0 = ua[0], A1 = ua[1];   // u[c0]
            float4 B0 = ua[2], B1 = ua[3];   // u[c0+1]
            ull uu[8];
            uu[0] = pack2(A0.x, B0.x); uu[1] = pack2(A0.y, B0.y);
            uu[2] = pack2(A0.z, B0.z); uu[3] = pack2(A0.w, B0.w);
            uu[4] = pack2(A1.x, B1.x); uu[5] = pack2(A1.y, B1.y);
            uu[6] = pack2(A1.z, B1.z); uu[7] = pack2(A1.w, B1.w);
            float* uh0 = sUhat + o * O_STRIDE + c0 * UH_STRIDE;
            float* uh1 = uh0 + UH_STRIDE;
            const ull* wp = Wt + pair;
            #pragma unroll
            for (int d = 0; d < 16; ++d) {
                ull acc = pack2(0.f, 0.f);
                #pragma unroll
                for (int i = 0; i < 8; ++i)
                    ffma2(acc, wp[(d * 8 + i) * 960], uu[i]);
                float r0, r1;
                unpack2(acc, r0, r1);
                uh0[d] = r0;
                uh1[d] = r1;
            }
        }
    }
    for (int i = tid; i < 1920; i += NT) sB[i] = 0.f;
    __syncthreads();

    // ---- Phase 5: dynamic routing (3 iterations) ----
    for (int it = 0; it < 3; ++it) {
        // c = softmax over o (axis of size 5), per capsule c
        if (tid < 384) {
            float bb[5], m = -1e30f;
            #pragma unroll
            for (int o = 0; o < 5; ++o) { bb[o] = sB[o * 384 + tid]; m = fmaxf(m, bb[o]); }
            float e[5], ssum = 0.f;
            #pragma unroll
            for (int o = 0; o < 5; ++o) { e[o] = expf(bb[o] - m); ssum += e[o]; }
            float inv = 1.f / ssum;
            #pragma unroll
            for (int o = 0; o < 5; ++o) sC[o * 384 + tid] = e[o] * inv;
        }
        __syncthreads();
        // s[o][d] = sum_c c[o][c] * u_hat[o][c][d]  (6-way split over c)
        if (tid < 480) {
            int od = tid % 80, ch = tid / 80;
            int o = od >> 4, d = od & 15;
            const float* uh = sUhat + o * O_STRIDE + d;
            const float* cc = sC + o * 384;
            float acc = 0.f;
            int c0 = ch * 64;
            for (int c = c0; c < c0 + 64; ++c) acc += cc[c] * uh[c * UH_STRIDE];
            sSp[ch * 80 + od] = acc;
        }
        __syncthreads();
        if (tid < 80) {
            float s = 0.f;
            #pragma unroll
            for (int ch = 0; ch < 6; ++ch) s += sSp[ch * 80 + tid];
            sS[tid] = s;
        }
        __syncthreads();
        if (tid < 5) {
            float sq = 0.f;
            #pragma unroll
            for (int d = 0; d < 16; ++d) { float v = sS[tid * 16 + d]; sq += v * v; }
            sSq[tid] = sq;
        }
        __syncthreads();
        if (tid < 80) {
            int o = tid >> 4;
            float sq = sSq[o];
            float v = sS[tid] * (sq / (1.f + sq)) / (sqrtf(sq) + 1e-8f);
            sV[tid] = v;
            if (it == 2) out[(size_t)b * 80 + tid] = v;
        }
        __syncthreads();
        if (it < 2) {
            // b[o][c] += sum_d u_hat[o][c][d] * v[o][d]  (scalar, conflict-free)
            for (int p = tid; p < 1920; p += NT) {
                int o = p / 384;
                int c = p - o * 384;
                const float* uh = sUhat + o * O_STRIDE + c * UH_STRIDE;
                const float* vv = sV + o * 16;
                float acc = 0.f;
                #pragma unroll
                for (int q = 0; q < 16; ++q) acc += uh[q] * vv[q];
                sB[p] += acc;
            }
            __syncthreads();
        }
    }
}

extern "C" void kernel_launch(void* const* d_in, const int* in_sizes, int n_in,
                              void* d_out, int out_size) {
    const float* x  = (const float*)d_in[0];
    const float* w1 = (const float*)d_in[1];
    const float* b1 = (const float*)d_in[2];
    const float* w2 = (const float*)d_in[3];
    const float* b2 = (const float*)d_in[4];
    const float* W  = (const float*)d_in[5];
    float* out = (float*)d_out;

    int B = in_sizes[0] / 6400;

    size_t smem_bytes = SMEM_FLTS * sizeof(float);
    cudaFuncSetAttribute(caps_kernel, cudaFuncAttributeMaxDynamicSharedMemorySize,
                         (int)smem_bytes);

    int prep_n = W1S_N + W2P_N + WT2_N;
    prep_kernel<<<(prep_n + 255) / 256, 256>>>(w1, w2, W);
    caps_kernel<<<B, NT, smem_bytes>>>(x, b1, b2, out);
}